// round 5
// baseline (speedup 1.0000x reference)
#include <cuda_runtime.h>
#include <cuda_bf16.h>
#include <math.h>

// ---------------------------------------------------------------------------
// mean over all (i,j) of: same(i,j) ? max(1-cos,0) : cos, with cos = pairwise
// cosine of row-normalized inputs.
//
// Algebraic collapse (clamp provably inactive; rel_err==0.0 confirmed):
//   sum = S1.S2 + sum_c [ cnt1_c*cnt2_c - 2 * T1_c . T2_c ]
// T_c = class-sum of normalized rows.  O(N*D).
//
// R4: R3 profiled latency-bound on Phase-B pointer chasing (LDS->LDS->LDG
// dependent chains over variable-length buckets). Now rows are SORTED by
// class into packed 16B entries during the norm pass; Phase B walks the
// sorted list linearly: one broadcast LDS.128 + one independent L1-hit LDG
// per row, register accumulation, <=32 global REDs per block. No smem
// accumulator tile at all.
// ---------------------------------------------------------------------------

#define NCLASS   16
#define NCEFF    32           // 16 classes x 2 tensors
#define DIM      256
#define NBLOCKS  128
#define NTHREADS 256
#define ROWS_PB  64           // 8192 / 128

struct __align__(16) Entry {
    const float* ptr;
    float        inv;
    int          cls;
};

__device__ float        g_T[NCEFF * DIM];
__device__ int          g_cnt[NCEFF];
__device__ unsigned int g_done;

__global__ void __launch_bounds__(NTHREADS)
ci_kernel(const float* __restrict__ x1,
          const int* __restrict__ lab1, int n1,
          const float* __restrict__ x2,
          const int* __restrict__ lab2, int n2,
          float* __restrict__ out) {
    __shared__ Entry         sSorted[ROWS_PB];      // 1 KB
    __shared__ const float*  sPtr[ROWS_PB];
    __shared__ int           sCls[ROWS_PB];
    __shared__ int           sPos[ROWS_PB];
    __shared__ int           sCnt[NCEFF];
    __shared__ int           sOff[NCEFF];
    __shared__ unsigned int  sIsLast;
    __shared__ double        sRed[NTHREADS / 32];

    const int tid  = threadIdx.x;
    const int lane = tid & 31;
    const int wid  = tid >> 5;

    if (tid < NCEFF) sCnt[tid] = 0;
    __syncthreads();

    const int ntot  = n1 + n2;
    const int base  = blockIdx.x * ROWS_PB;
    const int chunk = min(ROWS_PB, ntot - base);

    // ---- prologue: labels, pointers, class counts, ranks (64 threads) -----
    if (tid < chunk) {
        int row = base + tid;
        const float* xp;
        int c;
        if (row < n1) { xp = x1 + (size_t)row * DIM;        c = lab1[row] & (NCLASS - 1); }
        else          { xp = x2 + (size_t)(row - n1) * DIM; c = (lab2[row - n1] & (NCLASS - 1)) + NCLASS; }
        sPtr[tid] = xp;
        sCls[tid] = c;
        sPos[tid] = atomicAdd(&sCnt[c], 1);
    }
    __syncthreads();

    // ---- warp 0: exclusive prefix scan of class counts -> bucket offsets --
    if (wid == 0) {
        int v = sCnt[lane];
        int s = v;
        #pragma unroll
        for (int o = 1; o < 32; o <<= 1) {
            int u = __shfl_up_sync(0xFFFFFFFFu, s, o);
            if (lane >= o) s += u;
        }
        sOff[lane] = s - v;   // exclusive
    }
    __syncthreads();

    // ---- norm pass: warp per row; write packed entry into sorted slot -----
    #pragma unroll
    for (int it = 0; it < ROWS_PB / (NTHREADS / 32); it++) {
        int i = it * (NTHREADS / 32) + wid;
        if (i >= chunk) break;
        const float* xp = sPtr[i];
        const float4* p = reinterpret_cast<const float4*>(xp);
        float4 a = p[lane * 2];
        float4 b = p[lane * 2 + 1];
        float ss = a.x * a.x + a.y * a.y + a.z * a.z + a.w * a.w
                 + b.x * b.x + b.y * b.y + b.z * b.z + b.w * b.w;
        #pragma unroll
        for (int o = 16; o > 0; o >>= 1)
            ss += __shfl_xor_sync(0xFFFFFFFFu, ss, o);
        if (lane == 0) {
            int c   = sCls[i];
            int idx = sOff[c] + sPos[i];
            sSorted[idx].ptr = xp;
            sSorted[idx].inv = 1.0f / fmaxf(sqrtf(ss), 1e-8f);
            sSorted[idx].cls = c;
        }
    }
    __syncthreads();

    // ---- Phase B: dim-owned register accumulation over sorted runs --------
    // thread owns dim d0 = tid; all loads are L1 hits from the norm pass.
    const int d0 = tid;
    for (int c = 0; c < NCEFF; c++) {
        int s = sOff[c];
        int e = s + sCnt[c];
        if (s == e) continue;
        float acc0 = 0.0f, acc1 = 0.0f;
        int k = s;
        for (; k + 1 < e; k += 2) {
            Entry e0 = sSorted[k];       // broadcast LDS.128
            Entry e1 = sSorted[k + 1];
            acc0 += e0.ptr[d0] * e0.inv; // independent L1-hit LDGs
            acc1 += e1.ptr[d0] * e1.inv;
        }
        if (k < e) {
            Entry e0 = sSorted[k];
            acc0 += e0.ptr[d0] * e0.inv;
        }
        atomicAdd(&g_T[c * DIM + d0], acc0 + acc1);   // RED, no return
    }
    if (tid < NCEFF) {
        int v = sCnt[tid];
        if (v) atomicAdd(&g_cnt[tid], v);
    }

    // ---- last-block election ----------------------------------------------
    __threadfence();
    __syncthreads();
    if (tid == 0)
        sIsLast = (atomicAdd(&g_done, 1u) == (unsigned)(NBLOCKS - 1));
    __syncthreads();
    if (!sIsLast) return;

    // ---- finalize (producer writes fenced + visible) -----------------------
    const int d = tid;  // 0..255 == DIM
    double s1 = 0.0, s2 = 0.0, t = 0.0;
    #pragma unroll
    for (int c = 0; c < NCLASS; c++) {
        double av = (double)g_T[c * DIM + d];
        double bv = (double)g_T[(c + NCLASS) * DIM + d];
        s1 += av;
        s2 += bv;
        t  += av * bv;
    }
    double part = s1 * s2 - 2.0 * t;
    #pragma unroll
    for (int o = 16; o > 0; o >>= 1)
        part += __shfl_xor_sync(0xFFFFFFFFu, part, o);
    if (lane == 0) sRed[wid] = part;
    __syncthreads();
    if (tid == 0) {
        double tot = 0.0;
        #pragma unroll
        for (int w = 0; w < NTHREADS / 32; w++) tot += sRed[w];
        double cc = 0.0;
        #pragma unroll
        for (int c = 0; c < NCLASS; c++)
            cc += (double)g_cnt[c] * (double)g_cnt[c + NCLASS];
        out[0] = (float)((tot + cc) / ((double)n1 * (double)n2));
    }
    __syncthreads();   // all threads done reading scratch

    // ---- re-zero scratch for next graph replay -----------------------------
    for (int i = tid; i < NCEFF * DIM; i += NTHREADS)
        g_T[i] = 0.0f;
    if (tid < NCEFF) g_cnt[tid] = 0;
    if (tid == 0) g_done = 0u;
}

extern "C" void kernel_launch(void* const* d_in, const int* in_sizes, int n_in,
                              void* d_out, int out_size) {
    const float* mmd1 = (const float*)d_in[0];
    const float* mmd2 = (const float*)d_in[1];
    const int*   lab1 = (const int*)d_in[2];
    const int*   lab2 = (const int*)d_in[3];

    int n1 = in_sizes[0] / DIM;
    int n2 = in_sizes[1] / DIM;

    ci_kernel<<<NBLOCKS, NTHREADS>>>(mmd1, lab1, n1, mmd2, lab2, n2,
                                     (float*)d_out);
}

// round 6
// speedup vs baseline: 1.0472x; 1.0472x over previous
#include <cuda_runtime.h>
#include <cuda_bf16.h>
#include <math.h>

// ---------------------------------------------------------------------------
// mean over all (i,j) of: same(i,j) ? max(1-cos,0) : cos, with cos = pairwise
// cosine of row-normalized inputs.
//
// Algebraic collapse (clamp provably inactive; rel_err==0.0 confirmed):
//   sum = S1.S2 + sum_c [ cnt1_c*cnt2_c - 2 * T1_c . T2_c ]
// T_c = class-sum of normalized rows.  O(N*D).
//
// R5: R3/R4 profiles showed dur == 8MB / 289GB/s exactly -> the kernel is a
// latency-bound DRAM read (MLP ~2 per warp; shuffle chain gated load issue).
// Fix: each warp FRONT-BATCHES all 16 LDG.128s for its 8 rows into registers
// (8KB/warp in flight, 64KB/SM >> the ~11.5KB/SM needed for full HBM BW),
// then runs the 8 independent shuffle reductions.
// ---------------------------------------------------------------------------

#define NCLASS   16
#define NCEFF    32           // 16 classes x 2 tensors
#define DIM      256
#define NBLOCKS  128
#define NTHREADS 256
#define ROWS_PB  64           // 8192 / 128
#define ROWS_PW  8            // rows per warp

struct __align__(16) Entry {
    const float* ptr;
    float        inv;
    int          cls;
};

__device__ float        g_T[NCEFF * DIM];
__device__ int          g_cnt[NCEFF];
__device__ unsigned int g_done;

__global__ void __launch_bounds__(NTHREADS, 1)
ci_kernel(const float* __restrict__ x1,
          const int* __restrict__ lab1, int n1,
          const float* __restrict__ x2,
          const int* __restrict__ lab2, int n2,
          float* __restrict__ out) {
    __shared__ Entry         sSorted[ROWS_PB];
    __shared__ const float*  sPtr[ROWS_PB];
    __shared__ int           sCls[ROWS_PB];
    __shared__ int           sPos[ROWS_PB];
    __shared__ int           sCnt[NCEFF];
    __shared__ int           sOff[NCEFF];
    __shared__ unsigned int  sIsLast;
    __shared__ double        sRed[NTHREADS / 32];

    const int tid  = threadIdx.x;
    const int lane = tid & 31;
    const int wid  = tid >> 5;

    if (tid < NCEFF) sCnt[tid] = 0;
    __syncthreads();

    const int ntot  = n1 + n2;
    const int base  = blockIdx.x * ROWS_PB;
    const int chunk = min(ROWS_PB, ntot - base);

    // ---- prologue: labels, pointers, class counts, ranks (64 threads) -----
    if (tid < chunk) {
        int row = base + tid;
        const float* xp;
        int c;
        if (row < n1) { xp = x1 + (size_t)row * DIM;        c = lab1[row] & (NCLASS - 1); }
        else          { xp = x2 + (size_t)(row - n1) * DIM; c = (lab2[row - n1] & (NCLASS - 1)) + NCLASS; }
        sPtr[tid] = xp;
        sCls[tid] = c;
        sPos[tid] = atomicAdd(&sCnt[c], 1);
    }
    __syncthreads();

    // ---- warp 0: exclusive prefix scan of class counts -> bucket offsets --
    if (wid == 0) {
        int v = sCnt[lane];
        int s = v;
        #pragma unroll
        for (int o = 1; o < 32; o <<= 1) {
            int u = __shfl_up_sync(0xFFFFFFFFu, s, o);
            if (lane >= o) s += u;
        }
        sOff[lane] = s - v;   // exclusive
    }
    __syncthreads();

    // ---- norm pass: warp handles 8 rows; ALL loads front-batched ----------
    {
        const int i0 = wid * ROWS_PW;   // warp's first row in block chunk
        const float4* ps[ROWS_PW];
        #pragma unroll
        for (int j = 0; j < ROWS_PW; j++) {
            int i = i0 + j;
            // safe dummy pointer for OOB rows (never written back)
            ps[j] = reinterpret_cast<const float4*>(i < chunk ? sPtr[i] : x1);
        }

        float4 A[ROWS_PW], B[ROWS_PW];
        #pragma unroll
        for (int j = 0; j < ROWS_PW; j++) {
            A[j] = ps[j][lane * 2];        // 16 independent LDG.128s,
            B[j] = ps[j][lane * 2 + 1];    // front-batched by ptxas
        }

        float ss[ROWS_PW];
        #pragma unroll
        for (int j = 0; j < ROWS_PW; j++) {
            ss[j] = A[j].x * A[j].x + A[j].y * A[j].y + A[j].z * A[j].z + A[j].w * A[j].w
                  + B[j].x * B[j].x + B[j].y * B[j].y + B[j].z * B[j].z + B[j].w * B[j].w;
        }
        // 8 independent shuffle reductions (pipelined)
        #pragma unroll
        for (int o = 16; o > 0; o >>= 1) {
            #pragma unroll
            for (int j = 0; j < ROWS_PW; j++)
                ss[j] += __shfl_xor_sync(0xFFFFFFFFu, ss[j], o);
        }
        if (lane == 0) {
            #pragma unroll
            for (int j = 0; j < ROWS_PW; j++) {
                int i = i0 + j;
                if (i < chunk) {
                    int c   = sCls[i];
                    int idx = sOff[c] + sPos[i];
                    sSorted[idx].ptr = (const float*)ps[j];
                    sSorted[idx].inv = 1.0f / fmaxf(sqrtf(ss[j]), 1e-8f);
                    sSorted[idx].cls = c;
                }
            }
        }
    }
    __syncthreads();

    // ---- Phase B: dim-owned register accumulation over sorted runs --------
    // thread owns dim d0 = tid; loads are L1 hits from the norm pass.
    const int d0 = tid;
    for (int c = 0; c < NCEFF; c++) {
        int s = sOff[c];
        int e = s + sCnt[c];
        if (s == e) continue;
        float acc0 = 0.0f, acc1 = 0.0f;
        int k = s;
        for (; k + 1 < e; k += 2) {
            Entry e0 = sSorted[k];         // broadcast LDS.128
            Entry e1 = sSorted[k + 1];
            acc0 += e0.ptr[d0] * e0.inv;   // independent L1-hit LDGs
            acc1 += e1.ptr[d0] * e1.inv;
        }
        if (k < e) {
            Entry e0 = sSorted[k];
            acc0 += e0.ptr[d0] * e0.inv;
        }
        atomicAdd(&g_T[c * DIM + d0], acc0 + acc1);   // RED, no return
    }
    if (tid < NCEFF) {
        int v = sCnt[tid];
        if (v) atomicAdd(&g_cnt[tid], v);
    }

    // ---- last-block election ----------------------------------------------
    __threadfence();
    __syncthreads();
    if (tid == 0)
        sIsLast = (atomicAdd(&g_done, 1u) == (unsigned)(NBLOCKS - 1));
    __syncthreads();
    if (!sIsLast) return;

    // ---- finalize (producer writes fenced + visible) -----------------------
    const int d = tid;  // 0..255 == DIM
    double s1 = 0.0, s2 = 0.0, t = 0.0;
    #pragma unroll
    for (int c = 0; c < NCLASS; c++) {
        double av = (double)g_T[c * DIM + d];
        double bv = (double)g_T[(c + NCLASS) * DIM + d];
        s1 += av;
        s2 += bv;
        t  += av * bv;
    }
    double part = s1 * s2 - 2.0 * t;
    #pragma unroll
    for (int o = 16; o > 0; o >>= 1)
        part += __shfl_xor_sync(0xFFFFFFFFu, part, o);
    if (lane == 0) sRed[wid] = part;
    __syncthreads();
    if (tid == 0) {
        double tot = 0.0;
        #pragma unroll
        for (int w = 0; w < NTHREADS / 32; w++) tot += sRed[w];
        double cc = 0.0;
        #pragma unroll
        for (int c = 0; c < NCLASS; c++)
            cc += (double)g_cnt[c] * (double)g_cnt[c + NCLASS];
        out[0] = (float)((tot + cc) / ((double)n1 * (double)n2));
    }
    __syncthreads();   // all threads done reading scratch

    // ---- re-zero scratch for next graph replay -----------------------------
    for (int i = tid; i < NCEFF * DIM; i += NTHREADS)
        g_T[i] = 0.0f;
    if (tid < NCEFF) g_cnt[tid] = 0;
    if (tid == 0) g_done = 0u;
}

extern "C" void kernel_launch(void* const* d_in, const int* in_sizes, int n_in,
                              void* d_out, int out_size) {
    const float* mmd1 = (const float*)d_in[0];
    const float* mmd2 = (const float*)d_in[1];
    const int*   lab1 = (const int*)d_in[2];
    const int*   lab2 = (const int*)d_in[3];

    int n1 = in_sizes[0] / DIM;
    int n2 = in_sizes[1] / DIM;

    ci_kernel<<<NBLOCKS, NTHREADS>>>(mmd1, lab1, n1, mmd2, lab2, n2,
                                     (float*)d_out);
}

// round 7
// speedup vs baseline: 1.1386x; 1.0873x over previous
#include <cuda_runtime.h>
#include <cuda_bf16.h>
#include <math.h>

// ---------------------------------------------------------------------------
// mean over all (i,j) of: same(i,j) ? max(1-cos,0) : cos, with cos = pairwise
// cosine of row-normalized inputs.
//
// Algebraic collapse (clamp provably inactive; rel_err==0.0 confirmed):
//   sum = S1.S2 + sum_c [ cnt1_c*cnt2_c - 2 * T1_c . T2_c ]
// T_c = class-sum of normalized rows.  O(N*D).
//
// R6: R3/R4/R5 all pinned at ~27us with every ncu meter near zero ->
// latency-serialized phase chain at 1 block/SM (occ 12.5%). Fix: 16-row
// blocks, 512 blocks => ~4 co-resident blocks/SM overlap each other's
// phases. RED contention mitigated with 4 g_T replicas.
// ---------------------------------------------------------------------------

#define NCLASS   16
#define NCEFF    32           // 16 classes x 2 tensors
#define DIM      256
#define NBLOCKS  512
#define NTHREADS 256
#define ROWS_PB  16
#define NREP     4            // g_T replicas (cuts RED per-address depth 4x)

struct __align__(16) Entry {
    const float* ptr;
    float        inv;
    int          cls;
};

__device__ float        g_T[NREP][NCEFF * DIM];
__device__ int          g_cnt[NREP][NCEFF];
__device__ unsigned int g_done;

__global__ void __launch_bounds__(NTHREADS)
ci_kernel(const float* __restrict__ x1,
          const int* __restrict__ lab1, int n1,
          const float* __restrict__ x2,
          const int* __restrict__ lab2, int n2,
          float* __restrict__ out) {
    __shared__ Entry         sSorted[ROWS_PB];
    __shared__ const float*  sPtr[ROWS_PB];
    __shared__ int           sCls[ROWS_PB];
    __shared__ int           sPos[ROWS_PB];
    __shared__ int           sCnt[NCEFF];
    __shared__ int           sOff[NCEFF];
    __shared__ unsigned int  sIsLast;
    __shared__ double        sRed[NTHREADS / 32];

    const int tid  = threadIdx.x;
    const int lane = tid & 31;
    const int wid  = tid >> 5;
    const int rep  = blockIdx.x & (NREP - 1);

    if (tid < NCEFF) sCnt[tid] = 0;
    __syncthreads();

    const int ntot  = n1 + n2;
    const int base  = blockIdx.x * ROWS_PB;
    const int chunk = min(ROWS_PB, ntot - base);   // may be <= 0

    if (chunk > 0) {
        // ---- prologue: labels, pointers, counts, ranks (16 threads) -------
        if (tid < chunk) {
            int row = base + tid;
            const float* xp;
            int c;
            if (row < n1) { xp = x1 + (size_t)row * DIM;        c = lab1[row] & (NCLASS - 1); }
            else          { xp = x2 + (size_t)(row - n1) * DIM; c = (lab2[row - n1] & (NCLASS - 1)) + NCLASS; }
            sPtr[tid] = xp;
            sCls[tid] = c;
            sPos[tid] = atomicAdd(&sCnt[c], 1);
        }
        __syncthreads();

        // ---- warp 0: exclusive prefix scan of counts -> bucket offsets ----
        if (wid == 0) {
            int v = sCnt[lane];
            int s = v;
            #pragma unroll
            for (int o = 1; o < 32; o <<= 1) {
                int u = __shfl_up_sync(0xFFFFFFFFu, s, o);
                if (lane >= o) s += u;
            }
            sOff[lane] = s - v;   // exclusive
        }
        __syncthreads();

        // ---- norm pass: warp handles 2 rows, loads front-batched ----------
        {
            const int i0 = wid * 2;
            const float4* p0 = reinterpret_cast<const float4*>(
                (i0 < chunk) ? sPtr[i0] : x1);
            const float4* p1 = reinterpret_cast<const float4*>(
                (i0 + 1 < chunk) ? sPtr[i0 + 1] : x1);

            float4 A0 = p0[lane * 2], B0 = p0[lane * 2 + 1];
            float4 A1 = p1[lane * 2], B1 = p1[lane * 2 + 1];

            float s0 = A0.x * A0.x + A0.y * A0.y + A0.z * A0.z + A0.w * A0.w
                     + B0.x * B0.x + B0.y * B0.y + B0.z * B0.z + B0.w * B0.w;
            float s1 = A1.x * A1.x + A1.y * A1.y + A1.z * A1.z + A1.w * A1.w
                     + B1.x * B1.x + B1.y * B1.y + B1.z * B1.z + B1.w * B1.w;
            #pragma unroll
            for (int o = 16; o > 0; o >>= 1) {
                s0 += __shfl_xor_sync(0xFFFFFFFFu, s0, o);
                s1 += __shfl_xor_sync(0xFFFFFFFFu, s1, o);
            }
            if (lane == 0) {
                if (i0 < chunk) {
                    int c   = sCls[i0];
                    int idx = sOff[c] + sPos[i0];
                    sSorted[idx].ptr = (const float*)p0;
                    sSorted[idx].inv = 1.0f / fmaxf(sqrtf(s0), 1e-8f);
                    sSorted[idx].cls = c;
                }
                if (i0 + 1 < chunk) {
                    int c   = sCls[i0 + 1];
                    int idx = sOff[c] + sPos[i0 + 1];
                    sSorted[idx].ptr = (const float*)p1;
                    sSorted[idx].inv = 1.0f / fmaxf(sqrtf(s1), 1e-8f);
                    sSorted[idx].cls = c;
                }
            }
        }
        __syncthreads();

        // ---- Phase B: linear run-scan over sorted entries (dim per thread)
        // Loads are L1 hits from the norm pass. Uniform control flow.
        {
            const int d0 = tid;
            float acc = 0.0f;
            int prev = -1;
            for (int k = 0; k < chunk; k++) {
                Entry e = sSorted[k];               // broadcast LDS.128
                if (e.cls != prev) {
                    if (prev >= 0)
                        atomicAdd(&g_T[rep][prev * DIM + d0], acc);
                    acc = 0.0f;
                    prev = e.cls;
                }
                acc += e.ptr[d0] * e.inv;           // independent L1-hit LDG
            }
            if (prev >= 0)
                atomicAdd(&g_T[rep][prev * DIM + d0], acc);
        }
        if (tid < NCEFF) {
            int v = sCnt[tid];
            if (v) atomicAdd(&g_cnt[rep][tid], v);
        }
    }

    // ---- last-block election (ALL blocks participate) ----------------------
    __threadfence();
    __syncthreads();
    if (tid == 0)
        sIsLast = (atomicAdd(&g_done, 1u) == (unsigned)(NBLOCKS - 1));
    __syncthreads();
    if (!sIsLast) return;

    // ---- finalize (producer writes fenced + visible) ------------------------
    const int d = tid;  // 0..255 == DIM
    double s1 = 0.0, s2 = 0.0, t = 0.0;
    #pragma unroll
    for (int c = 0; c < NCLASS; c++) {
        float av = 0.0f, bv = 0.0f;
        #pragma unroll
        for (int r = 0; r < NREP; r++) {
            av += g_T[r][c * DIM + d];
            bv += g_T[r][(c + NCLASS) * DIM + d];
        }
        double ad = (double)av, bd = (double)bv;
        s1 += ad;
        s2 += bd;
        t  += ad * bd;
    }
    double part = s1 * s2 - 2.0 * t;
    #pragma unroll
    for (int o = 16; o > 0; o >>= 1)
        part += __shfl_xor_sync(0xFFFFFFFFu, part, o);
    if (lane == 0) sRed[wid] = part;
    __syncthreads();
    if (tid == 0) {
        double tot = 0.0;
        #pragma unroll
        for (int w = 0; w < NTHREADS / 32; w++) tot += sRed[w];
        double cc = 0.0;
        #pragma unroll
        for (int c = 0; c < NCLASS; c++) {
            long long c1 = 0, c2 = 0;
            #pragma unroll
            for (int r = 0; r < NREP; r++) {
                c1 += g_cnt[r][c];
                c2 += g_cnt[r][c + NCLASS];
            }
            cc += (double)c1 * (double)c2;
        }
        out[0] = (float)((tot + cc) / ((double)n1 * (double)n2));
    }
    __syncthreads();   // all threads done reading scratch

    // ---- re-zero scratch for next graph replay ------------------------------
    for (int i = tid; i < NREP * NCEFF * DIM; i += NTHREADS)
        (&g_T[0][0])[i] = 0.0f;
    if (tid < NREP * NCEFF) (&g_cnt[0][0])[tid] = 0;
    if (tid == 0) g_done = 0u;
}

extern "C" void kernel_launch(void* const* d_in, const int* in_sizes, int n_in,
                              void* d_out, int out_size) {
    const float* mmd1 = (const float*)d_in[0];
    const float* mmd2 = (const float*)d_in[1];
    const int*   lab1 = (const int*)d_in[2];
    const int*   lab2 = (const int*)d_in[3];

    int n1 = in_sizes[0] / DIM;
    int n2 = in_sizes[1] / DIM;

    ci_kernel<<<NBLOCKS, NTHREADS>>>(mmd1, lab1, n1, mmd2, lab2, n2,
                                     (float*)d_out);
}

// round 8
// speedup vs baseline: 1.3542x; 1.1893x over previous
#include <cuda_runtime.h>
#include <cuda_bf16.h>
#include <math.h>

// ---------------------------------------------------------------------------
// mean over all (i,j) of: same(i,j) ? max(1-cos,0) : cos, with cos = pairwise
// cosine of row-normalized inputs.
//
// Algebraic collapse (clamp provably inactive; rel_err==0.0 confirmed):
//   sum = S1.S2 + sum_c [ cnt1_c*cnt2_c - 2 * T1_c . T2_c ]
// T_c = class-sum of normalized rows.  O(N*D).
//
// R7: R3-R6 share a ~20us floor with all ncu meters idle and (R6) a single
// fully-co-resident wave -> hypothesis: chip-wide serialization on the LTS
// atomic ALUs by ~1.4M scalar fp32 REDs (invisible to lts__throughput),
// with warps parked at MEMBAR waiting for RED drain. This round flushes
// via red.global.add.v4.f32 (4 floats/op, ~4x fewer LTS atomic ops),
// all else identical to R6.
// ---------------------------------------------------------------------------

#define NCLASS   16
#define NCEFF    32           // 16 classes x 2 tensors
#define DIM      256
#define DIMQ     (DIM / 4)    // 64 dim-quads
#define NBLOCKS  512
#define NTHREADS 256
#define ROWS_PB  16
#define NREP     4            // g_T replicas

struct __align__(16) Entry {
    const float* ptr;
    float        inv;
    int          cls;
};

__device__ float4       g_T4[NREP][NCEFF * DIMQ];   // [4][32*64] quads
__device__ int          g_cnt[NREP][NCEFF];
__device__ unsigned int g_done;

__device__ __forceinline__ void red_v4(float4* p, float4 v) {
    asm volatile("red.global.add.v4.f32 [%0], {%1, %2, %3, %4};"
                 :: "l"(p), "f"(v.x), "f"(v.y), "f"(v.z), "f"(v.w)
                 : "memory");
}

__global__ void __launch_bounds__(NTHREADS)
ci_kernel(const float* __restrict__ x1,
          const int* __restrict__ lab1, int n1,
          const float* __restrict__ x2,
          const int* __restrict__ lab2, int n2,
          float* __restrict__ out) {
    __shared__ Entry         sSorted[ROWS_PB];
    __shared__ const float*  sPtr[ROWS_PB];
    __shared__ int           sCls[ROWS_PB];
    __shared__ int           sPos[ROWS_PB];
    __shared__ int           sCnt[NCEFF];
    __shared__ int           sOff[NCEFF];
    __shared__ unsigned int  sIsLast;
    __shared__ double        sRed[NTHREADS / 32];

    const int tid  = threadIdx.x;
    const int lane = tid & 31;
    const int wid  = tid >> 5;
    const int rep  = blockIdx.x & (NREP - 1);

    if (tid < NCEFF) sCnt[tid] = 0;
    __syncthreads();

    const int ntot  = n1 + n2;
    const int base  = blockIdx.x * ROWS_PB;
    const int chunk = min(ROWS_PB, ntot - base);   // may be <= 0

    if (chunk > 0) {
        // ---- prologue: labels, pointers, counts, ranks (16 threads) -------
        if (tid < chunk) {
            int row = base + tid;
            const float* xp;
            int c;
            if (row < n1) { xp = x1 + (size_t)row * DIM;        c = lab1[row] & (NCLASS - 1); }
            else          { xp = x2 + (size_t)(row - n1) * DIM; c = (lab2[row - n1] & (NCLASS - 1)) + NCLASS; }
            sPtr[tid] = xp;
            sCls[tid] = c;
            sPos[tid] = atomicAdd(&sCnt[c], 1);
        }
        __syncthreads();

        // ---- warp 0: exclusive prefix scan of counts -> bucket offsets ----
        if (wid == 0) {
            int v = sCnt[lane];
            int s = v;
            #pragma unroll
            for (int o = 1; o < 32; o <<= 1) {
                int u = __shfl_up_sync(0xFFFFFFFFu, s, o);
                if (lane >= o) s += u;
            }
            sOff[lane] = s - v;   // exclusive
        }
        __syncthreads();

        // ---- norm pass: warp handles 2 rows, loads front-batched ----------
        {
            const int i0 = wid * 2;
            const float4* p0 = reinterpret_cast<const float4*>(
                (i0 < chunk) ? sPtr[i0] : x1);
            const float4* p1 = reinterpret_cast<const float4*>(
                (i0 + 1 < chunk) ? sPtr[i0 + 1] : x1);

            float4 A0 = p0[lane * 2], B0 = p0[lane * 2 + 1];
            float4 A1 = p1[lane * 2], B1 = p1[lane * 2 + 1];

            float s0 = A0.x * A0.x + A0.y * A0.y + A0.z * A0.z + A0.w * A0.w
                     + B0.x * B0.x + B0.y * B0.y + B0.z * B0.z + B0.w * B0.w;
            float s1 = A1.x * A1.x + A1.y * A1.y + A1.z * A1.z + A1.w * A1.w
                     + B1.x * B1.x + B1.y * B1.y + B1.z * B1.z + B1.w * B1.w;
            #pragma unroll
            for (int o = 16; o > 0; o >>= 1) {
                s0 += __shfl_xor_sync(0xFFFFFFFFu, s0, o);
                s1 += __shfl_xor_sync(0xFFFFFFFFu, s1, o);
            }
            if (lane == 0) {
                if (i0 < chunk) {
                    int c   = sCls[i0];
                    int idx = sOff[c] + sPos[i0];
                    sSorted[idx].ptr = (const float*)p0;
                    sSorted[idx].inv = 1.0f / fmaxf(sqrtf(s0), 1e-8f);
                    sSorted[idx].cls = c;
                }
                if (i0 + 1 < chunk) {
                    int c   = sCls[i0 + 1];
                    int idx = sOff[c] + sPos[i0 + 1];
                    sSorted[idx].ptr = (const float*)p1;
                    sSorted[idx].inv = 1.0f / fmaxf(sqrtf(s1), 1e-8f);
                    sSorted[idx].cls = c;
                }
            }
        }
        __syncthreads();

        // ---- Phase B: 4 row-groups x 64 dim-quads; run-scan; v4 REDs -------
        // group g handles sorted rows [4g, 4g+4); thread owns dim-quad q.
        {
            const int g = tid >> 6;        // 0..3
            const int q = tid & (DIMQ - 1);
            int s = g * 4;
            int e = min(s + 4, chunk);
            float4 acc = make_float4(0.f, 0.f, 0.f, 0.f);
            int prev = -1;
            for (int k = s; k < e; k++) {
                Entry en = sSorted[k];                       // broadcast LDS.128
                if (en.cls != prev) {
                    if (prev >= 0)
                        red_v4(&g_T4[rep][prev * DIMQ + q], acc);
                    acc = make_float4(0.f, 0.f, 0.f, 0.f);
                    prev = en.cls;
                }
                float4 v = reinterpret_cast<const float4*>(en.ptr)[q];  // L1 hit
                acc.x += v.x * en.inv;
                acc.y += v.y * en.inv;
                acc.z += v.z * en.inv;
                acc.w += v.w * en.inv;
            }
            if (prev >= 0)
                red_v4(&g_T4[rep][prev * DIMQ + q], acc);
        }
        if (tid < NCEFF) {
            int v = sCnt[tid];
            if (v) atomicAdd(&g_cnt[rep][tid], v);
        }
    }

    // ---- last-block election (ALL blocks participate) ----------------------
    __threadfence();
    __syncthreads();
    if (tid == 0)
        sIsLast = (atomicAdd(&g_done, 1u) == (unsigned)(NBLOCKS - 1));
    __syncthreads();
    if (!sIsLast) return;

    // ---- finalize (producer writes fenced + visible) ------------------------
    const float* gT = (const float*)&g_T4[0][0];   // [NREP][NCEFF*DIM] floats
    const int d = tid;  // 0..255 == DIM
    double s1 = 0.0, s2 = 0.0, t = 0.0;
    #pragma unroll
    for (int c = 0; c < NCLASS; c++) {
        float av = 0.0f, bv = 0.0f;
        #pragma unroll
        for (int r = 0; r < NREP; r++) {
            av += gT[(r * NCEFF + c) * DIM + d];
            bv += gT[(r * NCEFF + c + NCLASS) * DIM + d];
        }
        double ad = (double)av, bd = (double)bv;
        s1 += ad;
        s2 += bd;
        t  += ad * bd;
    }
    double part = s1 * s2 - 2.0 * t;
    #pragma unroll
    for (int o = 16; o > 0; o >>= 1)
        part += __shfl_xor_sync(0xFFFFFFFFu, part, o);
    if (lane == 0) sRed[wid] = part;
    __syncthreads();
    if (tid == 0) {
        double tot = 0.0;
        #pragma unroll
        for (int w = 0; w < NTHREADS / 32; w++) tot += sRed[w];
        double cc = 0.0;
        #pragma unroll
        for (int c = 0; c < NCLASS; c++) {
            long long c1 = 0, c2 = 0;
            #pragma unroll
            for (int r = 0; r < NREP; r++) {
                c1 += g_cnt[r][c];
                c2 += g_cnt[r][c + NCLASS];
            }
            cc += (double)c1 * (double)c2;
        }
        out[0] = (float)((tot + cc) / ((double)n1 * (double)n2));
    }
    __syncthreads();   // all threads done reading scratch

    // ---- re-zero scratch for next graph replay ------------------------------
    for (int i = tid; i < NREP * NCEFF * DIMQ; i += NTHREADS)
        (&g_T4[0][0])[i] = make_float4(0.f, 0.f, 0.f, 0.f);
    if (tid < NREP * NCEFF) (&g_cnt[0][0])[tid] = 0;
    if (tid == 0) g_done = 0u;
}

extern "C" void kernel_launch(void* const* d_in, const int* in_sizes, int n_in,
                              void* d_out, int out_size) {
    const float* mmd1 = (const float*)d_in[0];
    const float* mmd2 = (const float*)d_in[1];
    const int*   lab1 = (const int*)d_in[2];
    const int*   lab2 = (const int*)d_in[3];

    int n1 = in_sizes[0] / DIM;
    int n2 = in_sizes[1] / DIM;

    ci_kernel<<<NBLOCKS, NTHREADS>>>(mmd1, lab1, n1, mmd2, lab2, n2,
                                     (float*)d_out);
}